// round 15
// baseline (speedup 1.0000x reference)
#include <cuda_runtime.h>
#include <cuda_fp16.h>
#include <mma.h>
#include <math.h>
#include <stdint.h>

using namespace nvcuda;

// Problem constants
#define N_TOK 8192
#define DIM   512
#define FDIM  2048
#define NEXP  8
#define NASS  (N_TOK * 2)
#define EPS_F 2.220446049250313e-16f

// Dynamic smem layout (hal号/bytes):
//  As: 2 stages x 128 rows x 40 halves  = 20480 B
//  Bs: 2 stages x  32 rows x 264 halves = 33792 B
//  scr: 8 warps x 256 floats            =  8192 B
#define AS_HALVES   (128 * 40)
#define BS_HALVES   (32 * 264)
#define BS_BYTE0    (2 * AS_HALVES * 2)
#define SCR_BYTE0   (BS_BYTE0 + 2 * BS_HALVES * 2)
#define SMEM_TOTAL  (SCR_BYTE0 + 8 * 256 * 4)

// ---------------- scratch (static device globals) ----------------
__device__ float g_H[(size_t)NASS * FDIM];   // relu(x@W1+b1), fp32
__device__ float g_O[(size_t)NASS * DIM];    // gate*exp(h@W2+b2), fp32
__device__ int   g_cnt[NEXP];                // zeroed at entry (combine re-zeroes)
__device__ int   g_off[NEXP];
__device__ int   g_cursor[NEXP];
__device__ int   g_tok_e[N_TOK * 2];
__device__ float g_tok_g[N_TOK * 2];
__device__ int   g_row_tok[NASS];
__device__ float g_row_gate[NASS];
__device__ int   g_ass_row[N_TOK * 2];

// ---------------- gating / routing (validated, unchanged) ----------------
__global__ void gate_kernel(const float* __restrict__ x, const float* __restrict__ Wg) {
    __shared__ float WgS[NEXP][DIM];
    int tid = threadIdx.x;
    for (int i = tid; i < DIM * NEXP; i += 256) {
        int d = i >> 3, e = i & 7;
        WgS[e][d] = Wg[i];
    }
    __syncthreads();
    int warp = tid >> 5, lane = tid & 31;
    int t = blockIdx.x * 8 + warp;
    float acc[NEXP];
#pragma unroll
    for (int e = 0; e < NEXP; e++) acc[e] = 0.f;
    const float* xr = x + (size_t)t * DIM;
    for (int j = lane; j < DIM; j += 32) {
        float xv = xr[j];
#pragma unroll
        for (int e = 0; e < NEXP; e++) acc[e] += xv * WgS[e][j];
    }
#pragma unroll
    for (int e = 0; e < NEXP; e++) {
#pragma unroll
        for (int o = 16; o > 0; o >>= 1) acc[e] += __shfl_xor_sync(0xffffffffu, acc[e], o);
    }
    if (lane == 0) {
        float best = -INFINITY, sec = -INFINITY;
        int bi = 0, si = 0;
#pragma unroll
        for (int e = 0; e < NEXP; e++) {
            float v = acc[e];
            if (v > best)     { sec = best; si = bi; best = v; bi = e; }
            else if (v > sec) { sec = v; si = e; }
        }
        float e1 = expf(sec - best);
        float s  = 1.f + e1;
        g_tok_e[2 * t] = bi;  g_tok_e[2 * t + 1] = si;
        g_tok_g[2 * t] = 1.f / s;  g_tok_g[2 * t + 1] = e1 / s;
        atomicAdd(&g_cnt[bi], 1);
        atomicAdd(&g_cnt[si], 1);
    }
}

__global__ void prefix_kernel() {
    int o = 0;
    for (int e = 0; e < NEXP; e++) { g_off[e] = o; g_cursor[e] = o; o += g_cnt[e]; }
}

__global__ void assign_kernel() {
    int t = blockIdx.x * 256 + threadIdx.x;
    int e0 = g_tok_e[2 * t], e1 = g_tok_e[2 * t + 1];
    int r0 = atomicAdd(&g_cursor[e0], 1);
    int r1 = atomicAdd(&g_cursor[e1], 1);
    g_row_tok[r0] = t; g_row_gate[r0] = g_tok_g[2 * t];
    g_row_tok[r1] = t; g_row_gate[r1] = g_tok_g[2 * t + 1];
    g_ass_row[2 * t] = r0;
    g_ass_row[2 * t + 1] = r1;
}

// ---------------- WMMA fp16 GEMM: CTA 128x256, warp tile 64x64 (8 warps = 2M x 4N) ----------------
// Rationale: 64x64 warp tile -> (4+4) fragment loads per 16 mmas = 256 B/mma LDSM traffic
// (vs 384 B/mma at 32x64) to relieve the measured 77% L1tex bound.
// C[m][n] = sum_k A[m][k]*B[k][n]; KC=32, double-buffered dynamic smem.
template<bool G1>
__global__ void moe_gemm_wmma(const float* __restrict__ x,
                              const float* __restrict__ W,
                              const float* __restrict__ bias) {
    constexpr int K    = G1 ? DIM : FDIM;
    constexpr int NOUT = G1 ? FDIM : DIM;
    constexpr int KT   = K / 32;

    extern __shared__ __align__(16) char smem[];
    __half* As  = (__half*)smem;               // [2][128*40]
    __half* Bs  = (__half*)(smem + BS_BYTE0);  // [2][32*264]
    float*  scr = (float*)(smem + SCR_BYTE0);  // [8][256]

    int e   = blockIdx.z;
    int cnt = g_cnt[e];
    int m0  = blockIdx.y * 128;
    if (m0 >= cnt) return;
    int base = g_off[e];
    int n0   = blockIdx.x * 256;

    const float* Bb = W + (size_t)e * ((size_t)DIM * FDIM);

    int tid = threadIdx.x, wid = tid >> 5, lane = tid & 31;
    int wm = (wid & 1) * 64;     // 2 warps in M
    int wn = (wid >> 1) * 64;    // 4 warps in N

    // A staging rows (as R9): 1024 float4-chunks = 128 rows x 8, 4/thread
    int tok[4];
#pragma unroll
    for (int q = 0; q < 4; q++) {
        int ch = q * 256 + tid;
        int arow = ch >> 3;
        int mr = m0 + arow; if (mr >= cnt) mr = cnt - 1;
        tok[q] = G1 ? g_row_tok[base + mr] : (base + mr);
    }

    float4 ra[4], rb[8];
    auto gload = [&](int kt) {
#pragma unroll
        for (int q = 0; q < 4; q++) {
            int ch = q * 256 + tid;
            int ac = ch & 7;
            const float* arow_p = G1 ? (x + (size_t)tok[q] * DIM)
                                     : (g_H + (size_t)tok[q] * FDIM);
            ra[q] = __ldcg((const float4*)(arow_p + kt * 32 + ac * 4));
        }
        // B: 2048 float4-chunks = 32 rows x 64, 8/thread
#pragma unroll
        for (int q = 0; q < 8; q++) {
            int ch = q * 256 + tid;
            int brow = ch >> 6, bc = ch & 63;
            rb[q] = __ldcg((const float4*)(Bb + (size_t)(kt * 32 + brow) * NOUT + n0 + bc * 4));
        }
    };
    auto sstore = [&](int s) {
        __half* as = As + s * AS_HALVES;
        __half* bs = Bs + s * BS_HALVES;
#pragma unroll
        for (int q = 0; q < 4; q++) {
            int ch = q * 256 + tid;
            int arow = ch >> 3, ac = ch & 7;
            __half2* ap = (__half2*)&as[arow * 40 + ac * 4];
            ap[0] = __floats2half2_rn(ra[q].x, ra[q].y);
            ap[1] = __floats2half2_rn(ra[q].z, ra[q].w);
        }
#pragma unroll
        for (int q = 0; q < 8; q++) {
            int ch = q * 256 + tid;
            int brow = ch >> 6, bc = ch & 63;
            __half2* bp = (__half2*)&bs[brow * 264 + bc * 4];
            bp[0] = __floats2half2_rn(rb[q].x, rb[q].y);
            bp[1] = __floats2half2_rn(rb[q].z, rb[q].w);
        }
    };

    wmma::fragment<wmma::accumulator, 16, 16, 16, float> acc[4][4];
#pragma unroll
    for (int mi = 0; mi < 4; mi++)
#pragma unroll
        for (int nj = 0; nj < 4; nj++) wmma::fill_fragment(acc[mi][nj], 0.f);

    gload(0);

#pragma unroll 1
    for (int kt = 0; kt < KT; kt++) {
        int s = kt & 1;
        __syncthreads();
        sstore(s);
        __syncthreads();
        if (kt + 1 < KT) gload(kt + 1);

        const __half* as = As + s * AS_HALVES;
        const __half* bs = Bs + s * BS_HALVES;
#pragma unroll
        for (int kk = 0; kk < 2; kk++) {
            wmma::fragment<wmma::matrix_b, 16, 16, 16, __half, wmma::row_major> bf[4];
#pragma unroll
            for (int nj = 0; nj < 4; nj++)
                wmma::load_matrix_sync(bf[nj], &bs[(kk * 16) * 264 + wn + nj * 16], 264);
#pragma unroll
            for (int mi = 0; mi < 4; mi++) {
                wmma::fragment<wmma::matrix_a, 16, 16, 16, __half, wmma::row_major> af;
                wmma::load_matrix_sync(af, &as[(wm + mi * 16) * 40 + kk * 16], 40);
#pragma unroll
                for (int nj = 0; nj < 4; nj++)
                    wmma::mma_sync(acc[mi][nj], af, bf[nj], acc[mi][nj]);
            }
        }
    }

    // ---------------- vectorized epilogue via per-warp smem scratch ----------------
    __syncthreads();
    float* scrW = scr + wid * 256;
    const float* be = bias + (size_t)e * NOUT + n0;
    int rr = lane >> 2;            // rows 0..7
    int cc = (lane & 3) * 4;       // float4 column chunk
#pragma unroll
    for (int mi = 0; mi < 4; mi++) {
#pragma unroll
        for (int nj = 0; nj < 4; nj++) {
            wmma::store_matrix_sync(scrW, acc[mi][nj], 16, wmma::mem_row_major);
            __syncwarp();
            int mbase = m0 + wm + mi * 16;
#pragma unroll
            for (int h = 0; h < 2; h++) {
                int row = rr + h * 8;
                int m = mbase + row;
                if (m < cnt) {
                    int r = base + m;
                    int nc = wn + nj * 16 + cc;
                    float4 v = *(const float4*)&scrW[row * 16 + cc];
                    float4 bv = *(const float4*)&be[nc];
                    v.x += bv.x; v.y += bv.y; v.z += bv.z; v.w += bv.w;
                    if (G1) {
                        v.x = v.x > 0.f ? v.x : 0.f;
                        v.y = v.y > 0.f ? v.y : 0.f;
                        v.z = v.z > 0.f ? v.z : 0.f;
                        v.w = v.w > 0.f ? v.w : 0.f;
                        *(float4*)&g_H[(size_t)r * FDIM + n0 + nc] = v;
                    } else {
                        float gate = g_row_gate[r];
                        v.x = gate * __expf(v.x);
                        v.y = gate * __expf(v.y);
                        v.z = gate * __expf(v.z);
                        v.w = gate * __expf(v.w);
                        *(float4*)&g_O[(size_t)r * DIM + n0 + nc] = v;
                    }
                }
            }
            __syncwarp();
        }
    }
}

// ---------------- combine (float4) + counter re-zero ----------------
__global__ void combine_kernel(float* __restrict__ out) {
    int i = blockIdx.x * 256 + threadIdx.x;
    int idx = i * 4;
    int t = idx >> 9;
    int d = idx & (DIM - 1);
    int r0 = g_ass_row[2 * t];
    int r1 = g_ass_row[2 * t + 1];
    float4 a = *(const float4*)&g_O[(size_t)r0 * DIM + d];
    float4 b = *(const float4*)&g_O[(size_t)r1 * DIM + d];
    float4 v;
    float s0 = a.x + b.x, s1 = a.y + b.y, s2 = a.z + b.z, s3 = a.w + b.w;
    v.x = logf(s0 == 0.f ? EPS_F : s0);
    v.y = logf(s1 == 0.f ? EPS_F : s1);
    v.z = logf(s2 == 0.f ? EPS_F : s2);
    v.w = logf(s3 == 0.f ? EPS_F : s3);
    *(float4*)&out[idx] = v;
    if (blockIdx.x == 0 && threadIdx.x < NEXP) g_cnt[threadIdx.x] = 0;
}

// ---------------- launch ----------------
extern "C" void kernel_launch(void* const* d_in, const int* in_sizes, int n_in,
                              void* d_out, int out_size) {
    const float* x  = (const float*)d_in[0];
    const float* Wg = (const float*)d_in[1];
    const float* W1 = (const float*)d_in[2];
    const float* b1 = (const float*)d_in[3];
    const float* W2 = (const float*)d_in[4];
    const float* b2 = (const float*)d_in[5];
    float* out = (float*)d_out;

    cudaFuncSetAttribute(moe_gemm_wmma<true>,  cudaFuncAttributeMaxDynamicSharedMemorySize, SMEM_TOTAL);
    cudaFuncSetAttribute(moe_gemm_wmma<false>, cudaFuncAttributeMaxDynamicSharedMemorySize, SMEM_TOTAL);

    gate_kernel<<<N_TOK / 8, 256>>>(x, Wg);       // 1
    prefix_kernel<<<1, 1>>>();                     // 2
    assign_kernel<<<N_TOK / 256, 256>>>();         // 3
    moe_gemm_wmma<true ><<<dim3(FDIM / 256, 64, NEXP), 256, SMEM_TOTAL>>>(x, W1, b1);  // 4 -> ncu
    moe_gemm_wmma<false><<<dim3(DIM  / 256, 64, NEXP), 256, SMEM_TOTAL>>>(x, W2, b2);  // 5
    combine_kernel<<<(N_TOK * DIM / 4) / 256, 256>>>(out);                              // 6
}

// round 16
// speedup vs baseline: 1.4461x; 1.4461x over previous
#include <cuda_runtime.h>
#include <cuda_fp16.h>
#include <mma.h>
#include <math.h>
#include <stdint.h>

using namespace nvcuda;

// Problem constants
#define N_TOK 8192
#define DIM   512
#define FDIM  2048
#define NEXP  8
#define NASS  (N_TOK * 2)
#define EPS_F 2.220446049250313e-16f

// ---------------- scratch (static device globals) ----------------
__device__ float g_H[(size_t)NASS * FDIM];   // relu(x@W1+b1), fp32
__device__ float g_O[(size_t)NASS * DIM];    // gate*exp(h@W2+b2), fp32
__device__ int   g_cnt[NEXP];                // zeroed at entry (combine re-zeroes)
__device__ int   g_off[NEXP];
__device__ int   g_cursor[NEXP];
__device__ int   g_tok_e[N_TOK * 2];
__device__ float g_tok_g[N_TOK * 2];
__device__ int   g_row_tok[NASS];
__device__ float g_row_gate[NASS];
__device__ int   g_ass_row[N_TOK * 2];

// ---------------- gating / routing (validated, unchanged) ----------------
__global__ void gate_kernel(const float* __restrict__ x, const float* __restrict__ Wg) {
    __shared__ float WgS[NEXP][DIM];
    int tid = threadIdx.x;
    for (int i = tid; i < DIM * NEXP; i += 256) {
        int d = i >> 3, e = i & 7;
        WgS[e][d] = Wg[i];
    }
    __syncthreads();
    int warp = tid >> 5, lane = tid & 31;
    int t = blockIdx.x * 8 + warp;
    float acc[NEXP];
#pragma unroll
    for (int e = 0; e < NEXP; e++) acc[e] = 0.f;
    const float* xr = x + (size_t)t * DIM;
    for (int j = lane; j < DIM; j += 32) {
        float xv = xr[j];
#pragma unroll
        for (int e = 0; e < NEXP; e++) acc[e] += xv * WgS[e][j];
    }
#pragma unroll
    for (int e = 0; e < NEXP; e++) {
#pragma unroll
        for (int o = 16; o > 0; o >>= 1) acc[e] += __shfl_xor_sync(0xffffffffu, acc[e], o);
    }
    if (lane == 0) {
        float best = -INFINITY, sec = -INFINITY;
        int bi = 0, si = 0;
#pragma unroll
        for (int e = 0; e < NEXP; e++) {
            float v = acc[e];
            if (v > best)     { sec = best; si = bi; best = v; bi = e; }
            else if (v > sec) { sec = v; si = e; }
        }
        float e1 = expf(sec - best);
        float s  = 1.f + e1;
        g_tok_e[2 * t] = bi;  g_tok_e[2 * t + 1] = si;
        g_tok_g[2 * t] = 1.f / s;  g_tok_g[2 * t + 1] = e1 / s;
        atomicAdd(&g_cnt[bi], 1);
        atomicAdd(&g_cnt[si], 1);
    }
}

__global__ void prefix_kernel() {
    int o = 0;
    for (int e = 0; e < NEXP; e++) { g_off[e] = o; g_cursor[e] = o; o += g_cnt[e]; }
}

__global__ void assign_kernel() {
    int t = blockIdx.x * 256 + threadIdx.x;
    int e0 = g_tok_e[2 * t], e1 = g_tok_e[2 * t + 1];
    int r0 = atomicAdd(&g_cursor[e0], 1);
    int r1 = atomicAdd(&g_cursor[e1], 1);
    g_row_tok[r0] = t; g_row_gate[r0] = g_tok_g[2 * t];
    g_row_tok[r1] = t; g_row_gate[r1] = g_tok_g[2 * t + 1];
    g_ass_row[2 * t] = r0;
    g_ass_row[2 * t + 1] = r1;
}

// ---------------- WMMA fp16 GEMM: CTA 128x128, 128 threads (4 warps = 2M x 2N of 64x64) ----------------
// 64x64 warp tile -> 8 fragment loads / 16 mmas (LDSM relief, validated in R15),
// 4-warp CTAs x2 per SM -> two independent barrier domains (fixes R15's exposed latency).
template<bool G1>
__global__ __launch_bounds__(128, 2) void moe_gemm_wmma(const float* __restrict__ x,
                                                        const float* __restrict__ W,
                                                        const float* __restrict__ bias) {
    constexpr int K    = G1 ? DIM : FDIM;
    constexpr int NOUT = G1 ? FDIM : DIM;
    constexpr int KT   = K / 32;

    __shared__ __align__(32) __half As[2][128 * 40];   // ldm 40
    __shared__ __align__(32) __half Bs[2][32 * 136];   // ldm 136
    __shared__ __align__(32) float  scr[4][16 * 16];

    int e   = blockIdx.z;
    int cnt = g_cnt[e];
    int m0  = blockIdx.y * 128;
    if (m0 >= cnt) return;
    int base = g_off[e];
    int n0   = blockIdx.x * 128;

    const float* Bb = W + (size_t)e * ((size_t)DIM * FDIM);

    int tid = threadIdx.x, wid = tid >> 5, lane = tid & 31;
    int wm = (wid & 1) * 64;     // 2 warps in M
    int wn = (wid >> 1) * 64;    // 2 warps in N

    // A staging: 1024 float4-chunks = 128 rows x 8, 8/thread
    int tok[8];
#pragma unroll
    for (int q = 0; q < 8; q++) {
        int ch = q * 128 + tid;
        int arow = ch >> 3;
        int mr = m0 + arow; if (mr >= cnt) mr = cnt - 1;
        tok[q] = G1 ? g_row_tok[base + mr] : (base + mr);
    }

    float4 ra[8], rb[8];
    auto gload = [&](int kt) {
#pragma unroll
        for (int q = 0; q < 8; q++) {
            int ch = q * 128 + tid;
            int ac = ch & 7;
            const float* arow_p = G1 ? (x + (size_t)tok[q] * DIM)
                                     : (g_H + (size_t)tok[q] * FDIM);
            ra[q] = __ldcg((const float4*)(arow_p + kt * 32 + ac * 4));
            // B: 1024 chunks = 32 rows x 32, 8/thread
            int brow = ch >> 5, bc = ch & 31;
            rb[q] = __ldcg((const float4*)(Bb + (size_t)(kt * 32 + brow) * NOUT + n0 + bc * 4));
        }
    };
    auto sstore = [&](int s) {
#pragma unroll
        for (int q = 0; q < 8; q++) {
            int ch = q * 128 + tid;
            int arow = ch >> 3, ac = ch & 7;
            __half2* ap = (__half2*)&As[s][arow * 40 + ac * 4];
            ap[0] = __floats2half2_rn(ra[q].x, ra[q].y);
            ap[1] = __floats2half2_rn(ra[q].z, ra[q].w);
            int brow = ch >> 5, bc = ch & 31;
            __half2* bp = (__half2*)&Bs[s][brow * 136 + bc * 4];
            bp[0] = __floats2half2_rn(rb[q].x, rb[q].y);
            bp[1] = __floats2half2_rn(rb[q].z, rb[q].w);
        }
    };

    wmma::fragment<wmma::accumulator, 16, 16, 16, float> acc[4][4];
#pragma unroll
    for (int mi = 0; mi < 4; mi++)
#pragma unroll
        for (int nj = 0; nj < 4; nj++) wmma::fill_fragment(acc[mi][nj], 0.f);

    gload(0);

#pragma unroll 1
    for (int kt = 0; kt < KT; kt++) {
        int s = kt & 1;
        __syncthreads();
        sstore(s);
        __syncthreads();
        if (kt + 1 < KT) gload(kt + 1);

#pragma unroll
        for (int kk = 0; kk < 2; kk++) {
            wmma::fragment<wmma::matrix_b, 16, 16, 16, __half, wmma::row_major> bf[4];
#pragma unroll
            for (int nj = 0; nj < 4; nj++)
                wmma::load_matrix_sync(bf[nj], &Bs[s][(kk * 16) * 136 + wn + nj * 16], 136);
#pragma unroll
            for (int mi = 0; mi < 4; mi++) {
                wmma::fragment<wmma::matrix_a, 16, 16, 16, __half, wmma::row_major> af;
                wmma::load_matrix_sync(af, &As[s][(wm + mi * 16) * 40 + kk * 16], 40);
#pragma unroll
                for (int nj = 0; nj < 4; nj++)
                    wmma::mma_sync(acc[mi][nj], af, bf[nj], acc[mi][nj]);
            }
        }
    }

    // ---------------- vectorized epilogue via per-warp smem scratch ----------------
    __syncthreads();
    const float* be = bias + (size_t)e * NOUT + n0;
    int rr = lane >> 2;            // rows 0..7
    int cc = (lane & 3) * 4;       // float4 column chunk
#pragma unroll
    for (int mi = 0; mi < 4; mi++) {
#pragma unroll
        for (int nj = 0; nj < 4; nj++) {
            wmma::store_matrix_sync(&scr[wid][0], acc[mi][nj], 16, wmma::mem_row_major);
            __syncwarp();
            int mbase = m0 + wm + mi * 16;
#pragma unroll
            for (int h = 0; h < 2; h++) {
                int row = rr + h * 8;
                int m = mbase + row;
                if (m < cnt) {
                    int r = base + m;
                    int nc = wn + nj * 16 + cc;
                    float4 v = *(const float4*)&scr[wid][row * 16 + cc];
                    float4 bv = *(const float4*)&be[nc];
                    v.x += bv.x; v.y += bv.y; v.z += bv.z; v.w += bv.w;
                    if (G1) {
                        v.x = v.x > 0.f ? v.x : 0.f;
                        v.y = v.y > 0.f ? v.y : 0.f;
                        v.z = v.z > 0.f ? v.z : 0.f;
                        v.w = v.w > 0.f ? v.w : 0.f;
                        *(float4*)&g_H[(size_t)r * FDIM + n0 + nc] = v;
                    } else {
                        float gate = g_row_gate[r];
                        v.x = gate * __expf(v.x);
                        v.y = gate * __expf(v.y);
                        v.z = gate * __expf(v.z);
                        v.w = gate * __expf(v.w);
                        *(float4*)&g_O[(size_t)r * DIM + n0 + nc] = v;
                    }
                }
            }
            __syncwarp();
        }
    }
}

// ---------------- combine (float4) + counter re-zero ----------------
__global__ void combine_kernel(float* __restrict__ out) {
    int i = blockIdx.x * 256 + threadIdx.x;
    int idx = i * 4;
    int t = idx >> 9;
    int d = idx & (DIM - 1);
    int r0 = g_ass_row[2 * t];
    int r1 = g_ass_row[2 * t + 1];
    float4 a = *(const float4*)&g_O[(size_t)r0 * DIM + d];
    float4 b = *(const float4*)&g_O[(size_t)r1 * DIM + d];
    float4 v;
    float s0 = a.x + b.x, s1 = a.y + b.y, s2 = a.z + b.z, s3 = a.w + b.w;
    v.x = logf(s0 == 0.f ? EPS_F : s0);
    v.y = logf(s1 == 0.f ? EPS_F : s1);
    v.z = logf(s2 == 0.f ? EPS_F : s2);
    v.w = logf(s3 == 0.f ? EPS_F : s3);
    *(float4*)&out[idx] = v;
    if (blockIdx.x == 0 && threadIdx.x < NEXP) g_cnt[threadIdx.x] = 0;
}

// ---------------- launch ----------------
extern "C" void kernel_launch(void* const* d_in, const int* in_sizes, int n_in,
                              void* d_out, int out_size) {
    const float* x  = (const float*)d_in[0];
    const float* Wg = (const float*)d_in[1];
    const float* W1 = (const float*)d_in[2];
    const float* b1 = (const float*)d_in[3];
    const float* W2 = (const float*)d_in[4];
    const float* b2 = (const float*)d_in[5];
    float* out = (float*)d_out;

    gate_kernel<<<N_TOK / 8, 256>>>(x, Wg);       // 1
    prefix_kernel<<<1, 1>>>();                     // 2
    assign_kernel<<<N_TOK / 256, 256>>>();         // 3
    moe_gemm_wmma<true ><<<dim3(FDIM / 128, 64, NEXP), 128>>>(x, W1, b1);  // 4 -> ncu slot
    moe_gemm_wmma<false><<<dim3(DIM  / 128, 64, NEXP), 128>>>(x, W2, b2);  // 5
    combine_kernel<<<(N_TOK * DIM / 4) / 256, 256>>>(out);                  // 6
}